// round 4
// baseline (speedup 1.0000x reference)
#include <cuda_runtime.h>
#include <cstdint>

#define B_ 128
#define T_ 128
#define D_ 2048
#define U_ 512

// Scratch (static device globals -- no allocation allowed)
__device__ float g_xp[(size_t)B_ * T_ * U_];       // [B,T,U] input projection
__device__ float g_hraw[2][B_][U_];                // double-buffered raw state exchange
__device__ float g_part[2][16][8][8][2];           // [buf][cluster][rank][row][{sum,sumsq}]

// ---------------------------------------------------------------------------
// Phase 1: x_proj = x @ w_in + b      (M=16384, K=2048, N=512, fp32 SGEMM)
// Block tile 128x128, BK=16, 256 threads, per-thread 8x8 microkernel,
// register-prefetch double buffering on the global loads.
// ---------------------------------------------------------------------------
__global__ __launch_bounds__(256) void xproj_kernel(
    const float* __restrict__ A,    // x  [16384, 2048]
    const float* __restrict__ Bw,   // w_in [2048, 512]
    const float* __restrict__ bias) // [512]
{
    __shared__ float As[16][132];   // transposed A tile, padded
    __shared__ float Bs[16][128];

    const int tid = threadIdx.x;
    const int m0 = blockIdx.y * 128;
    const int n0 = blockIdx.x * 128;
    const int tx = tid & 15;        // N direction (tx*8)
    const int ty = tid >> 4;        // M direction (ty*8)

    // Per-thread load coordinates (fixed across k-tiles)
    const int ar0 = (tid) >> 2;               // A row for fragment 0
    const int ar1 = (256 + tid) >> 2;         // A row for fragment 1
    const int ac  = (tid & 3) << 2;           // A col-within-tile
    const int br0 = (tid) >> 5;               // B row for fragment 0
    const int br1 = (256 + tid) >> 5;         // B row for fragment 1
    const int bc  = (tid & 31) << 2;          // B col-within-tile

    const float4* Aptr0 = reinterpret_cast<const float4*>(A + (size_t)(m0 + ar0) * D_ + ac);
    const float4* Aptr1 = reinterpret_cast<const float4*>(A + (size_t)(m0 + ar1) * D_ + ac);
    const float4* Bptr0 = reinterpret_cast<const float4*>(Bw + (size_t)br0 * U_ + n0 + bc);
    const float4* Bptr1 = reinterpret_cast<const float4*>(Bw + (size_t)br1 * U_ + n0 + bc);

    float acc[8][8];
#pragma unroll
    for (int i = 0; i < 8; i++)
#pragma unroll
        for (int j = 0; j < 8; j++) acc[i][j] = 0.f;

    // Prefetch tile 0 (x is streamed: read-once, evict-first)
    float4 pa0 = __ldcs(Aptr0);
    float4 pa1 = __ldcs(Aptr1);
    float4 pb0 = *Bptr0;
    float4 pb1 = *Bptr1;

    for (int k0 = 0; k0 < D_; k0 += 16) {
        // Commit prefetched tile to smem
        As[ac + 0][ar0] = pa0.x; As[ac + 1][ar0] = pa0.y;
        As[ac + 2][ar0] = pa0.z; As[ac + 3][ar0] = pa0.w;
        As[ac + 0][ar1] = pa1.x; As[ac + 1][ar1] = pa1.y;
        As[ac + 2][ar1] = pa1.z; As[ac + 3][ar1] = pa1.w;
        *reinterpret_cast<float4*>(&Bs[br0][bc]) = pb0;
        *reinterpret_cast<float4*>(&Bs[br1][bc]) = pb1;
        __syncthreads();

        // Issue next tile's global loads (latency hidden behind compute)
        if (k0 + 16 < D_) {
            pa0 = __ldcs(Aptr0 + (k0 + 16) / 4);
            pa1 = __ldcs(Aptr1 + (k0 + 16) / 4);
            pb0 = *(Bptr0 + (size_t)(k0 + 16) * U_ / 4);
            pb1 = *(Bptr1 + (size_t)(k0 + 16) * U_ / 4);
        }

#pragma unroll
        for (int k = 0; k < 16; k++) {
            float a[8], b[8];
            float4 a0 = *reinterpret_cast<float4*>(&As[k][ty * 8]);
            float4 a1 = *reinterpret_cast<float4*>(&As[k][ty * 8 + 4]);
            a[0] = a0.x; a[1] = a0.y; a[2] = a0.z; a[3] = a0.w;
            a[4] = a1.x; a[5] = a1.y; a[6] = a1.z; a[7] = a1.w;
            float4 b0 = *reinterpret_cast<float4*>(&Bs[k][tx * 8]);
            float4 b1 = *reinterpret_cast<float4*>(&Bs[k][tx * 8 + 4]);
            b[0] = b0.x; b[1] = b0.y; b[2] = b0.z; b[3] = b0.w;
            b[4] = b1.x; b[5] = b1.y; b[6] = b1.z; b[7] = b1.w;
#pragma unroll
            for (int i = 0; i < 8; i++)
#pragma unroll
                for (int j = 0; j < 8; j++) acc[i][j] += a[i] * b[j];
        }
        __syncthreads();
    }

    float4 bv0 = *reinterpret_cast<const float4*>(bias + n0 + tx * 8);
    float4 bv1 = *reinterpret_cast<const float4*>(bias + n0 + tx * 8 + 4);
#pragma unroll
    for (int i = 0; i < 8; i++) {
        float4 o0, o1;
        o0.x = acc[i][0] + bv0.x; o0.y = acc[i][1] + bv0.y;
        o0.z = acc[i][2] + bv0.z; o0.w = acc[i][3] + bv0.w;
        o1.x = acc[i][4] + bv1.x; o1.y = acc[i][5] + bv1.y;
        o1.z = acc[i][6] + bv1.z; o1.w = acc[i][7] + bv1.w;
        float* orow = g_xp + (size_t)(m0 + ty * 8 + i) * U_ + n0 + tx * 8;
        *reinterpret_cast<float4*>(orow)     = o0;
        *reinterpret_cast<float4*>(orow + 4) = o1;
    }
}

// ---------------------------------------------------------------------------
// Phase 2: the liquid-cell scan.
// 16 clusters x 8 CTAs. Cluster c owns B-rows [8c, 8c+8). CTA rank r owns
// U-columns [64r, 64r+64) with its w_rec slice persistent (k-major) in SMEM.
// One cluster barrier per timestep; raw state + LN partial sums exchanged
// through L2 (double-buffered).
// ---------------------------------------------------------------------------
__device__ __forceinline__ void cluster_sync_() {
    asm volatile("barrier.cluster.arrive.aligned;" ::: "memory");
    asm volatile("barrier.cluster.wait.aligned;" ::: "memory");
}

__global__ void __cluster_dims__(8, 1, 1) __launch_bounds__(256, 1)
scan_kernel(const float* __restrict__ w_rec, const float* __restrict__ tau,
            const float* __restrict__ gamma, const float* __restrict__ beta,
            float* __restrict__ out)
{
    extern __shared__ float smbuf[];
    float* ws    = smbuf;              // [512][64]  w_rec slice (k-major)
    float* hnorm = ws + 512 * 64;      // [8][512]   normalized state (GEMM input)
    float* red   = hnorm + 8 * 512;    // [8][512]   k-split reduction buffer
    float* gsm   = red + 8 * 512;      // [512] gamma
    float* bsm   = gsm + 512;          // [512] beta
    float* wpart = bsm + 512;          // [16][4] per-warp LN partials
    float* stats = wpart + 64;         // [8][2] {mean, inv}

    const int tid = threadIdx.x;
    unsigned rank;
    asm("mov.u32 %0, %%cluster_ctarank;" : "=r"(rank));
    const int cl    = blockIdx.x >> 3;
    const int u0    = (int)rank * 64;
    const int brow0 = cl * 8;
    const int lane  = tid & 31;
    const int warp  = tid >> 5;        // k-split group: k in [warp*64, warp*64+64)
    const int k0    = warp * 64;
    const int up2   = lane * 2;        // u pair within slice

    // ---- one-time init ----
#pragma unroll
    for (int i = 0; i < 32; i++) {     // stage w_rec[:, u0:u0+64] -> ws (128 KB)
        int f = i * 256 + tid;         // float4 index over [512][16]
        int k = f >> 4;
        int uu = (f & 15) << 2;
        *reinterpret_cast<float4*>(ws + k * 64 + uu) =
            *reinterpret_cast<const float4*>(w_rec + (size_t)k * U_ + u0 + uu);
    }
    if (tid < 128) {
        *reinterpret_cast<float4*>(gsm + tid * 4) =
            *reinterpret_cast<const float4*>(gamma + tid * 4);
        *reinterpret_cast<float4*>(bsm + tid * 4) =
            *reinterpret_cast<const float4*>(beta + tid * 4);
    }
#pragma unroll
    for (int i = 0; i < 4; i++)        // h0 = 0
        *reinterpret_cast<float4*>(hnorm + (i * 256 + tid) * 4) = make_float4(0.f, 0.f, 0.f, 0.f);

    const int uloc  = tid & 63;
    const int uglob = u0 + uloc;
    const int r1    = tid >> 6;        // rows for this thread's two outputs
    const int r2    = r1 + 4;
    const float tau_r = tau[uglob];
    __syncthreads();

    for (int t = 0; t < T_; t++) {
        // ---- GEMM: base[8][64] = hnorm[8][512] @ ws[512][64], k-split by warp ----
        float acc[8][2];
#pragma unroll
        for (int r = 0; r < 8; r++) { acc[r][0] = 0.f; acc[r][1] = 0.f; }
#pragma unroll
        for (int kk = 0; kk < 64; kk += 4) {
            const int kb = k0 + kk;
            float ha[8][4];
#pragma unroll
            for (int r = 0; r < 8; r++) {
                float4 h4 = *reinterpret_cast<const float4*>(hnorm + r * 512 + kb);
                ha[r][0] = h4.x; ha[r][1] = h4.y; ha[r][2] = h4.z; ha[r][3] = h4.w;
            }
#pragma unroll
            for (int j = 0; j < 4; j++) {
                float2 w2 = *reinterpret_cast<const float2*>(ws + (kb + j) * 64 + up2);
#pragma unroll
                for (int r = 0; r < 8; r++) {
                    acc[r][0] += ha[r][j] * w2.x;
                    acc[r][1] += ha[r][j] * w2.y;
                }
            }
        }
#pragma unroll
        for (int r = 0; r < 8; r++)
            *reinterpret_cast<float2*>(red + warp * 512 + r * 64 + up2) =
                make_float2(acc[r][0], acc[r][1]);
        __syncthreads();

        // ---- reduce k-split, elementwise liquid update ----
        const int buf = t & 1;
        float v[2];
#pragma unroll
        for (int c = 0; c < 2; c++) {
            int oid = tid + c * 256;
            float s = 0.f;
#pragma unroll
            for (int ks = 0; ks < 8; ks++) s += red[ks * 512 + oid];
            int r = (c == 0) ? r1 : r2;
            float base = s + g_xp[((size_t)(brow0 + r) * T_ + t) * U_ + uglob];
            float hp   = hnorm[r * 512 + uglob];
            float sig  = 1.f / (1.f + __expf(-base));
            float lt   = tau_r * sig + 1e-7f;
            v[c] = hp + (base - hp) * lt;
        }

        // raw state to L2 (double buffered)
        g_hraw[buf][brow0 + r1][uglob] = v[0];
        g_hraw[buf][brow0 + r2][uglob] = v[1];

        // ---- LN partial sums: warp butterflies ----
        float s1 = v[0], q1 = v[0] * v[0], s2 = v[1], q2 = v[1] * v[1];
#pragma unroll
        for (int off = 16; off > 0; off >>= 1) {
            s1 += __shfl_xor_sync(0xffffffffu, s1, off);
            q1 += __shfl_xor_sync(0xffffffffu, q1, off);
            s2 += __shfl_xor_sync(0xffffffffu, s2, off);
            q2 += __shfl_xor_sync(0xffffffffu, q2, off);
        }
        if (lane == 0) {
            wpart[warp * 4 + 0] = s1; wpart[warp * 4 + 1] = q1;
            wpart[warp * 4 + 2] = s2; wpart[warp * 4 + 3] = q2;
        }
        __syncthreads();
        if (tid < 8) {
            int r = tid;
            int w0   = (r < 4) ? (r * 2) : ((r - 4) * 2);
            int slot = (r < 4) ? 0 : 2;
            float s = wpart[w0 * 4 + slot]     + wpart[(w0 + 1) * 4 + slot];
            float q = wpart[w0 * 4 + slot + 1] + wpart[(w0 + 1) * 4 + slot + 1];
            g_part[buf][cl][rank][r][0] = s;
            g_part[buf][cl][rank][r][1] = q;
        }
        __threadfence();
        cluster_sync_();

        // ---- gather stats across the 8 CTAs, normalize full rows into hnorm ----
        if (tid < 8) {
            int r = tid;
            float s = 0.f, q = 0.f;
#pragma unroll
            for (int p = 0; p < 8; p++) {
                s += __ldcg(&g_part[buf][cl][p][r][0]);
                q += __ldcg(&g_part[buf][cl][p][r][1]);
            }
            float mean = s * (1.f / 512.f);
            float var  = q * (1.f / 512.f) - mean * mean;
            stats[r * 2 + 0] = mean;
            stats[r * 2 + 1] = rsqrtf(var + 1e-3f);
        }
        __syncthreads();
#pragma unroll
        for (int i = 0; i < 4; i++) {
            int f4 = i * 256 + tid;
            int r  = f4 >> 7;
            int k  = (f4 & 127) << 2;
            float4 raw = __ldcg(reinterpret_cast<const float4*>(&g_hraw[buf][brow0 + r][k]));
            float mean = stats[r * 2 + 0];
            float inv  = stats[r * 2 + 1];
            float4 g4 = *reinterpret_cast<const float4*>(gsm + k);
            float4 b4 = *reinterpret_cast<const float4*>(bsm + k);
            float4 hn;
            hn.x = g4.x * (raw.x - mean) * inv + b4.x;
            hn.y = g4.y * (raw.y - mean) * inv + b4.y;
            hn.z = g4.z * (raw.z - mean) * inv + b4.z;
            hn.w = g4.w * (raw.w - mean) * inv + b4.w;
            *reinterpret_cast<float4*>(hnorm + r * 512 + k) = hn;
        }
        __syncthreads();
    }

    // ---- h_last: each CTA writes its own U slice ----
    out[(size_t)(brow0 + r1) * U_ + uglob] = hnorm[r1 * 512 + uglob];
    out[(size_t)(brow0 + r2) * U_ + uglob] = hnorm[r2 * 512 + uglob];
}

// ---------------------------------------------------------------------------
extern "C" void kernel_launch(void* const* d_in, const int* in_sizes, int n_in,
                              void* d_out, int out_size)
{
    (void)in_sizes; (void)n_in; (void)out_size;
    const float* x     = (const float*)d_in[0];
    const float* w_in  = (const float*)d_in[1];
    const float* w_rec = (const float*)d_in[2];
    const float* b     = (const float*)d_in[3];
    const float* tau   = (const float*)d_in[4];
    const float* gamma = (const float*)d_in[5];
    const float* beta  = (const float*)d_in[6];
    float* out = (float*)d_out;

    const int smem_bytes = (512 * 64 + 8 * 512 + 8 * 512 + 512 + 512 + 64 + 16) * 4; // 168256
    cudaFuncSetAttribute(scan_kernel, cudaFuncAttributeMaxDynamicSharedMemorySize, smem_bytes);

    dim3 g1(U_ / 128, (B_ * T_) / 128);   // (4, 128) blocks
    xproj_kernel<<<g1, 256>>>(x, w_in, b);
    scan_kernel<<<128, 256, smem_bytes>>>(w_rec, tau, gamma, beta, out);
}

// round 8
// speedup vs baseline: 1.6250x; 1.6250x over previous
#include <cuda_runtime.h>
#include <cuda_bf16.h>
#include <cstdint>

#define B_ 128
#define T_ 128
#define D_ 2048
#define U_ 512

// Scratch (static device globals -- no allocation allowed)
__device__ float g_xp[(size_t)B_ * T_ * U_];       // [B,T,U] input projection
__device__ float g_hraw[2][B_][U_];                // double-buffered raw state exchange
__device__ float g_part[2][16][8][8][2];           // [buf][cluster][rank][row][{sum,sumsq}]

// ===========================================================================
// MMA helpers (bf16 m16n8k16)
// ===========================================================================
__device__ __forceinline__ unsigned smem_u32(const void* p) {
    return (unsigned)__cvta_generic_to_shared(p);
}
__device__ __forceinline__ void ldmx4(unsigned* r, unsigned addr) {
    asm volatile("ldmatrix.sync.aligned.m8n8.x4.shared.b16 {%0,%1,%2,%3}, [%4];"
        : "=r"(r[0]), "=r"(r[1]), "=r"(r[2]), "=r"(r[3]) : "r"(addr));
}
__device__ __forceinline__ void ldmx2t(unsigned* r, unsigned addr) {
    asm volatile("ldmatrix.sync.aligned.m8n8.x2.trans.shared.b16 {%0,%1}, [%2];"
        : "=r"(r[0]), "=r"(r[1]) : "r"(addr));
}
__device__ __forceinline__ void mma16816(float* c, const unsigned* a, const unsigned* b) {
    asm volatile("mma.sync.aligned.m16n8k16.row.col.f32.bf16.bf16.f32 "
        "{%0,%1,%2,%3}, {%4,%5,%6,%7}, {%8,%9}, {%0,%1,%2,%3};"
        : "+f"(c[0]), "+f"(c[1]), "+f"(c[2]), "+f"(c[3])
        : "r"(a[0]), "r"(a[1]), "r"(a[2]), "r"(a[3]), "r"(b[0]), "r"(b[1]));
}

// ---------------------------------------------------------------------------
// Phase 1: x_proj = x @ w_in + b  via bf16 3-term split on tensor cores.
// CTA tile 128(M)x128(N), k-block 32, 8 warps in 2x4 (warp tile 64x32),
// double-buffered smem, fp32->bf16 hi/lo conversion on the fly.
//   A(buf,prec) at (buf*2+prec)*10240            (128 rows x 40 bf16)
//   B(buf,prec) at 40960 + (buf*2+prec)*8704     (32 rows x 136 bf16)
// ---------------------------------------------------------------------------
#define XP_SMEM 75776

__global__ __launch_bounds__(256, 1) void xproj_kernel(
    const float* __restrict__ A,    // x  [16384, 2048]
    const float* __restrict__ Bw,   // w_in [2048, 512]
    const float* __restrict__ bias) // [512]
{
    extern __shared__ char xsm[];
    const int tid = threadIdx.x;
    const int m0  = blockIdx.y * 128;
    const int n0g = blockIdx.x * 128;
    const int lane = tid & 31;
    const int wid  = tid >> 5;
    const int wm   = wid & 1;       // 2 warps in M (64 rows each)
    const int wn   = wid >> 1;      // 4 warps in N (32 cols each)

    const float* aP[4];
    const float* bP[4];
    int arowi[4], acoli[4], browi[4], bcoli[4];
#pragma unroll
    for (int i = 0; i < 4; i++) {
        int f = i * 256 + tid;
        arowi[i] = f >> 3;          acoli[i] = (f & 7) << 2;
        browi[i] = f >> 5;          bcoli[i] = (f & 31) << 2;
        aP[i] = A  + (size_t)(m0 + arowi[i]) * D_ + acoli[i];
        bP[i] = Bw + (size_t)browi[i] * U_ + n0g + bcoli[i];
    }

    float acc[4][4][4];
#pragma unroll
    for (int mt = 0; mt < 4; mt++)
#pragma unroll
        for (int nt = 0; nt < 4; nt++)
#pragma unroll
            for (int q = 0; q < 4; q++) acc[mt][nt][q] = 0.f;

    float4 pa[4], pb[4];
#pragma unroll
    for (int i = 0; i < 4; i++) {
        pa[i] = *reinterpret_cast<const float4*>(aP[i]);
        pb[i] = *reinterpret_cast<const float4*>(bP[i]);
    }

    const int arow_base = wm * 64 + (lane & 15);
    const int acolblk   = (lane >> 4) * 8;

    for (int kb = 0; kb < 64; kb++) {
        const int buf = kb & 1;
        char* Ah = xsm + (buf * 2 + 0) * 10240;
        char* Al = xsm + (buf * 2 + 1) * 10240;
        char* Bh = xsm + 40960 + (buf * 2 + 0) * 8704;
        char* Bl = xsm + 40960 + (buf * 2 + 1) * 8704;

        // convert + store this k-block (hi/lo split)
#pragma unroll
        for (int i = 0; i < 4; i++) {
            float4 v = pa[i];
            __nv_bfloat16 hx = __float2bfloat16_rn(v.x), hy = __float2bfloat16_rn(v.y);
            __nv_bfloat16 hz = __float2bfloat16_rn(v.z), hw = __float2bfloat16_rn(v.w);
            __nv_bfloat16 lx = __float2bfloat16_rn(v.x - __bfloat162float(hx));
            __nv_bfloat16 ly = __float2bfloat16_rn(v.y - __bfloat162float(hy));
            __nv_bfloat16 lz = __float2bfloat16_rn(v.z - __bfloat162float(hz));
            __nv_bfloat16 lw = __float2bfloat16_rn(v.w - __bfloat162float(hw));
            int off = arowi[i] * 80 + acoli[i] * 2;
            __nv_bfloat162* dh = reinterpret_cast<__nv_bfloat162*>(Ah + off);
            __nv_bfloat162* dl = reinterpret_cast<__nv_bfloat162*>(Al + off);
            __nv_bfloat162 t0; t0.x = hx; t0.y = hy; dh[0] = t0;
            __nv_bfloat162 t1; t1.x = hz; t1.y = hw; dh[1] = t1;
            __nv_bfloat162 t2; t2.x = lx; t2.y = ly; dl[0] = t2;
            __nv_bfloat162 t3; t3.x = lz; t3.y = lw; dl[1] = t3;

            float4 w = pb[i];
            __nv_bfloat16 whx = __float2bfloat16_rn(w.x), why = __float2bfloat16_rn(w.y);
            __nv_bfloat16 whz = __float2bfloat16_rn(w.z), whw = __float2bfloat16_rn(w.w);
            __nv_bfloat16 wlx = __float2bfloat16_rn(w.x - __bfloat162float(whx));
            __nv_bfloat16 wly = __float2bfloat16_rn(w.y - __bfloat162float(why));
            __nv_bfloat16 wlz = __float2bfloat16_rn(w.z - __bfloat162float(whz));
            __nv_bfloat16 wlw = __float2bfloat16_rn(w.w - __bfloat162float(whw));
            int offb = browi[i] * 272 + bcoli[i] * 2;
            __nv_bfloat162* dbh = reinterpret_cast<__nv_bfloat162*>(Bh + offb);
            __nv_bfloat162* dbl = reinterpret_cast<__nv_bfloat162*>(Bl + offb);
            __nv_bfloat162 u0; u0.x = whx; u0.y = why; dbh[0] = u0;
            __nv_bfloat162 u1; u1.x = whz; u1.y = whw; dbh[1] = u1;
            __nv_bfloat162 u2; u2.x = wlx; u2.y = wly; dbl[0] = u2;
            __nv_bfloat162 u3; u3.x = wlz; u3.y = wlw; dbl[1] = u3;
        }
        __syncthreads();

        // prefetch next k-block (latency hidden behind MMAs)
        if (kb + 1 < 64) {
            int koff = (kb + 1) * 32;
#pragma unroll
            for (int i = 0; i < 4; i++) {
                pa[i] = *reinterpret_cast<const float4*>(aP[i] + koff);
                pb[i] = *reinterpret_cast<const float4*>(bP[i] + (size_t)koff * U_);
            }
        }

        // MMA on this buffer: xhi*whi + xlo*whi + xhi*wlo
        unsigned aHb = smem_u32(Ah), aLb = smem_u32(Al);
        unsigned bHb = smem_u32(Bh), bLb = smem_u32(Bl);
#pragma unroll
        for (int kh = 0; kh < 32; kh += 16) {
            unsigned bh[4][2], bl[4][2];
#pragma unroll
            for (int nt = 0; nt < 4; nt++) {
                unsigned boff = (unsigned)((kh + (lane & 15)) * 272 + (wn * 32 + nt * 8) * 2);
                ldmx2t(bh[nt], bHb + boff);
                ldmx2t(bl[nt], bLb + boff);
            }
#pragma unroll
            for (int mt = 0; mt < 4; mt++) {
                unsigned aoff = (unsigned)((arow_base + mt * 16) * 80 + (kh + acolblk) * 2);
                unsigned ah[4], al[4];
                ldmx4(ah, aHb + aoff);
                ldmx4(al, aLb + aoff);
#pragma unroll
                for (int nt = 0; nt < 4; nt++) {
                    mma16816(acc[mt][nt], ah, bh[nt]);
                    mma16816(acc[mt][nt], al, bh[nt]);
                    mma16816(acc[mt][nt], ah, bl[nt]);
                }
            }
        }
    }

    // epilogue: add bias, write fp32
#pragma unroll
    for (int mt = 0; mt < 4; mt++) {
#pragma unroll
        for (int nt = 0; nt < 4; nt++) {
            int rr = m0 + wm * 64 + mt * 16 + (lane >> 2);
            int cc = n0g + wn * 32 + nt * 8 + (lane & 3) * 2;
            float2 b2 = *reinterpret_cast<const float2*>(bias + cc);
            float2 o0, o1;
            o0.x = acc[mt][nt][0] + b2.x; o0.y = acc[mt][nt][1] + b2.y;
            o1.x = acc[mt][nt][2] + b2.x; o1.y = acc[mt][nt][3] + b2.y;
            *reinterpret_cast<float2*>(g_xp + (size_t)rr * U_ + cc)       = o0;
            *reinterpret_cast<float2*>(g_xp + (size_t)(rr + 8) * U_ + cc) = o1;
        }
    }
}

// ---------------------------------------------------------------------------
// Phase 2: the liquid-cell scan. 16 clusters x 8 CTAs, 512 threads (16 warps).
// CTA rank owns U-cols [64r,64r+64) with w_rec slice persistent in SMEM.
// 16-way k-split GEMM; g_xp prefetched before GEMM; one cluster barrier/step.
// ---------------------------------------------------------------------------
__device__ __forceinline__ void cluster_sync_() {
    asm volatile("barrier.cluster.arrive.aligned;" ::: "memory");
    asm volatile("barrier.cluster.wait.aligned;" ::: "memory");
}

#define SCAN_SMEM ((512*64 + 8*512 + 16*512 + 512 + 512 + 32 + 16) * 4)

__global__ void __cluster_dims__(8, 1, 1) __launch_bounds__(512, 1)
scan_kernel(const float* __restrict__ w_rec, const float* __restrict__ tau,
            const float* __restrict__ gamma, const float* __restrict__ beta,
            float* __restrict__ out)
{
    extern __shared__ float smbuf[];
    float* ws    = smbuf;              // [512][64]  w_rec slice (k-major)
    float* hnorm = ws + 512 * 64;      // [8][512]   normalized state
    float* red   = hnorm + 8 * 512;    // [16][512]  k-split reduction buffer
    float* gsm   = red + 16 * 512;     // [512] gamma
    float* bsm   = gsm + 512;          // [512] beta
    float* wpart = bsm + 512;          // [16][2] per-warp LN partials
    float* stats = wpart + 32;         // [8][2] {mean, inv}

    const int tid = threadIdx.x;
    unsigned rank;
    asm("mov.u32 %0, %%cluster_ctarank;" : "=r"(rank));
    const int cl    = blockIdx.x >> 3;
    const int u0    = (int)rank * 64;
    const int brow0 = cl * 8;
    const int lane  = tid & 31;
    const int warp  = tid >> 5;        // k-split: k in [warp*32, warp*32+32)
    const int k0w   = warp * 32;
    const int up2   = lane * 2;

    const int uloc  = tid & 63;
    const int uglob = u0 + uloc;
    const int r     = tid >> 6;        // this thread's row (one output/thread)

    // ---- one-time init ----
#pragma unroll
    for (int i = 0; i < 16; i++) {     // stage w_rec[:, u0:u0+64) -> ws (128 KB)
        int f = i * 512 + tid;         // float4 index over [512][16]
        int k = f >> 4;
        int uu = (f & 15) << 2;
        *reinterpret_cast<float4*>(ws + k * 64 + uu) =
            *reinterpret_cast<const float4*>(w_rec + (size_t)k * U_ + u0 + uu);
    }
    if (tid < 128) {
        *reinterpret_cast<float4*>(gsm + tid * 4) =
            *reinterpret_cast<const float4*>(gamma + tid * 4);
        *reinterpret_cast<float4*>(bsm + tid * 4) =
            *reinterpret_cast<const float4*>(beta + tid * 4);
    }
    reinterpret_cast<float4*>(hnorm)[tid] = make_float4(0.f, 0.f, 0.f, 0.f);
    const float tau_r = tau[uglob];
    __syncthreads();

    for (int t = 0; t < T_; t++) {
        // prefetch this step's input projection (hidden behind the GEMM)
        const float xp = __ldcg(&g_xp[((size_t)(brow0 + r) * T_ + t) * U_ + uglob]);

        // ---- GEMM: base[8][64] = hnorm[8][512] @ ws[512][64], 16-way k-split ----
        float acc[8][2];
#pragma unroll
        for (int rr = 0; rr < 8; rr++) { acc[rr][0] = 0.f; acc[rr][1] = 0.f; }
#pragma unroll
        for (int kk = 0; kk < 32; kk += 4) {
            const int kb = k0w + kk;
            float ha[8][4];
#pragma unroll
            for (int rr = 0; rr < 8; rr++) {
                float4 h4 = *reinterpret_cast<const float4*>(hnorm + rr * 512 + kb);
                ha[rr][0] = h4.x; ha[rr][1] = h4.y; ha[rr][2] = h4.z; ha[rr][3] = h4.w;
            }
#pragma unroll
            for (int j = 0; j < 4; j++) {
                float2 w2 = *reinterpret_cast<const float2*>(ws + (kb + j) * 64 + up2);
#pragma unroll
                for (int rr = 0; rr < 8; rr++) {
                    acc[rr][0] += ha[rr][j] * w2.x;
                    acc[rr][1] += ha[rr][j] * w2.y;
                }
            }
        }
#pragma unroll
        for (int rr = 0; rr < 8; rr++)
            *reinterpret_cast<float2*>(red + warp * 512 + rr * 64 + up2) =
                make_float2(acc[rr][0], acc[rr][1]);
        __syncthreads();

        // ---- reduce k-split (one output per thread), liquid update ----
        const int buf = t & 1;
        float s = 0.f;
#pragma unroll
        for (int ks = 0; ks < 16; ks++) s += red[ks * 512 + tid];
        float base = s + xp;
        float hp   = hnorm[r * 512 + uglob];
        float sig  = 1.f / (1.f + __expf(-base));
        float lt   = tau_r * sig + 1e-7f;
        float v    = hp + (base - hp) * lt;

        // raw state to L2 (double buffered)
        g_hraw[buf][brow0 + r][uglob] = v;

        // ---- LN partials: warp reductions (2 warps per row) ----
        float s1 = v, q1 = v * v;
#pragma unroll
        for (int off = 16; off > 0; off >>= 1) {
            s1 += __shfl_xor_sync(0xffffffffu, s1, off);
            q1 += __shfl_xor_sync(0xffffffffu, q1, off);
        }
        if (lane == 0) *reinterpret_cast<float2*>(wpart + warp * 2) = make_float2(s1, q1);
        __syncthreads();
        if (tid < 8) {
            float ss = wpart[(2 * tid) * 2]     + wpart[(2 * tid + 1) * 2];
            float qq = wpart[(2 * tid) * 2 + 1] + wpart[(2 * tid + 1) * 2 + 1];
            g_part[buf][cl][rank][tid][0] = ss;
            g_part[buf][cl][rank][tid][1] = qq;
        }
        __threadfence();
        cluster_sync_();

        // ---- gather stats across 8 CTAs, normalize full rows ----
        if (tid < 8) {
            float ss = 0.f, qq = 0.f;
#pragma unroll
            for (int p = 0; p < 8; p++) {
                ss += __ldcg(&g_part[buf][cl][p][tid][0]);
                qq += __ldcg(&g_part[buf][cl][p][tid][1]);
            }
            float mean = ss * (1.f / 512.f);
            float var  = qq * (1.f / 512.f) - mean * mean;
            stats[tid * 2 + 0] = mean;
            stats[tid * 2 + 1] = rsqrtf(var + 1e-3f);
        }
        __syncthreads();
#pragma unroll
        for (int i = 0; i < 2; i++) {
            int f4 = i * 512 + tid;
            int rr = f4 >> 7;
            int k  = (f4 & 127) << 2;
            float4 raw = __ldcg(reinterpret_cast<const float4*>(&g_hraw[buf][brow0 + rr][k]));
            float mean = stats[rr * 2 + 0];
            float inv  = stats[rr * 2 + 1];
            float4 g4 = *reinterpret_cast<const float4*>(gsm + k);
            float4 b4 = *reinterpret_cast<const float4*>(bsm + k);
            float4 hn;
            hn.x = g4.x * (raw.x - mean) * inv + b4.x;
            hn.y = g4.y * (raw.y - mean) * inv + b4.y;
            hn.z = g4.z * (raw.z - mean) * inv + b4.z;
            hn.w = g4.w * (raw.w - mean) * inv + b4.w;
            *reinterpret_cast<float4*>(hnorm + rr * 512 + k) = hn;
        }
        __syncthreads();
    }

    // ---- h_last: one element per thread ----
    out[(size_t)(brow0 + r) * U_ + uglob] = hnorm[r * 512 + uglob];
}

// ---------------------------------------------------------------------------
extern "C" void kernel_launch(void* const* d_in, const int* in_sizes, int n_in,
                              void* d_out, int out_size)
{
    (void)in_sizes; (void)n_in; (void)out_size;
    const float* x     = (const float*)d_in[0];
    const float* w_in  = (const float*)d_in[1];
    const float* w_rec = (const float*)d_in[2];
    const float* b     = (const float*)d_in[3];
    const float* tau   = (const float*)d_in[4];
    const float* gamma = (const float*)d_in[5];
    const float* beta  = (const float*)d_in[6];
    float* out = (float*)d_out;

    cudaFuncSetAttribute(xproj_kernel, cudaFuncAttributeMaxDynamicSharedMemorySize, XP_SMEM);
    cudaFuncSetAttribute(scan_kernel,  cudaFuncAttributeMaxDynamicSharedMemorySize, SCAN_SMEM);

    dim3 g1(U_ / 128, (B_ * T_) / 128);   // (4, 128) blocks
    xproj_kernel<<<g1, 256, XP_SMEM>>>(x, w_in, b);
    scan_kernel<<<128, 512, SCAN_SMEM>>>(w_rec, tau, gamma, beta, out);
}